// round 10
// baseline (speedup 1.0000x reference)
#include <cuda_runtime.h>
#include <math.h>
#include <stdint.h>

#define NB 8192
#define KN 32
#define HD 1024
#define TMA_ROWS 8                       // rows 24..31 via TMA bulk copy
#define LDG_ROWS 24                      // rows 0..23 via direct LDG
#define TMA_FLOATS (TMA_ROWS * HD)       // 8192 floats = 32 KB
#define TMA_BYTES  (TMA_FLOATS * 4)

__device__ __forceinline__ uint32_t smem_u32(const void* p) {
    return (uint32_t)__cvta_generic_to_shared(p);
}
__device__ __forceinline__ void mbar_init(uint32_t mbar, uint32_t count) {
    asm volatile("mbarrier.init.shared::cta.b64 [%0], %1;"
                 :: "r"(mbar), "r"(count) : "memory");
}
__device__ __forceinline__ void mbar_expect_tx(uint32_t mbar, uint32_t bytes) {
    asm volatile("mbarrier.arrive.expect_tx.shared::cta.b64 _, [%0], %1;"
                 :: "r"(mbar), "r"(bytes) : "memory");
}
__device__ __forceinline__ void bulk_g2s(uint32_t dst, const void* src,
                                         uint32_t bytes, uint32_t mbar) {
    asm volatile(
        "cp.async.bulk.shared::cta.global.mbarrier::complete_tx::bytes "
        "[%0], [%1], %2, [%3];"
        :: "r"(dst), "l"(src), "r"(bytes), "r"(mbar) : "memory");
}
__device__ __forceinline__ void mbar_wait(uint32_t mbar, uint32_t phase) {
    uint32_t done;
    do {
        asm volatile(
            "{\n\t.reg .pred p;\n\t"
            "mbarrier.try_wait.parity.acquire.cta.shared::cta.b64 p, [%1], %2, 0x989680;\n\t"
            "selp.b32 %0, 1, 0, p;\n\t}"
            : "=r"(done) : "r"(mbar), "r"(phase) : "memory");
    } while (!done);
}

__global__ __launch_bounds__(256, 3)
void mu_calc_kernel(
    const int*   __restrict__ vals,
    const float* __restrict__ distances,
    const float* __restrict__ cache_hidden,
    const float* __restrict__ hiddens,
    const float* __restrict__ W1,
    const float* __restrict__ b1,
    const float* __restrict__ W2,
    const float* __restrict__ b2,
    float*       __restrict__ out)
{
    __shared__ __align__(16) float s_tma[TMA_FLOATS];   // 32 KB TMA landing zone
    __shared__ __align__(16) float s_cache[HD];         // 4 KB cache_hidden[b]
    __shared__ float s_cd[KN];
    __shared__ float s_x[96];
    __shared__ int   s_vals[KN];
    __shared__ float s_h2[64];
    __shared__ float s_scale;
    __shared__ __align__(8) unsigned long long s_mbar;

    const int b    = blockIdx.x;
    const int tid  = threadIdx.x;
    const int warp = tid >> 5;
    const int lane = tid & 31;

    const uint32_t mb = smem_u32(&s_mbar);

    // ---- stage per-batch data + init mbar ----
    reinterpret_cast<float4*>(s_cache)[tid] =
        reinterpret_cast<const float4*>(cache_hidden + (size_t)b * HD)[tid];
    if (tid < KN) {
        s_vals[tid]   = vals[b * KN + tid];
        s_x[32 + tid] = distances[b * KN + tid];
    }
    if (tid == 0) {
        mbar_init(mb, 1);
        asm volatile("fence.proxy.async.shared::cta;" ::: "memory");
    }
    __syncthreads();

    const float* gsrc = hiddens + (size_t)b * KN * HD;

    // ---- fire the TMA path: rows 24..31 (32 KB) in one bulk copy ----
    if (tid == 0) {
        mbar_expect_tx(mb, TMA_BYTES);
        bulk_g2s(smem_u32(s_tma), gsrc + (size_t)LDG_ROWS * HD, TMA_BYTES, mb);
    }

    // cache row -> registers (reused for all 4 of this warp's rows)
    const float4* sc4 = reinterpret_cast<const float4*>(s_cache);
    float4 cv[8];
    #pragma unroll
    for (int i = 0; i < 8; i++) cv[i] = sc4[lane + 32 * i];

    // ---- LDG path: rows warp, warp+8, warp+16 interleaved ----
    const float4* h4 = reinterpret_cast<const float4*>(hiddens +
                        ((size_t)b * KN + warp) * HD);
    const int RS = (HD / 4) * 8;          // 8 rows apart, in float4 units

    float acc0 = 0.f, acc1 = 0.f, acc2 = 0.f;
    #pragma unroll
    for (int i = 0; i < 8; i++) {
        const int off = lane + 32 * i;
        float4 h0 = __ldcs(&h4[off]);
        float4 h1 = __ldcs(&h4[RS     + off]);
        float4 h2 = __ldcs(&h4[2 * RS + off]);
        const float4 c = cv[i];
        float d;
        d = c.x - h0.x; acc0 = fmaf(d, d, acc0);
        d = c.y - h0.y; acc0 = fmaf(d, d, acc0);
        d = c.z - h0.z; acc0 = fmaf(d, d, acc0);
        d = c.w - h0.w; acc0 = fmaf(d, d, acc0);
        d = c.x - h1.x; acc1 = fmaf(d, d, acc1);
        d = c.y - h1.y; acc1 = fmaf(d, d, acc1);
        d = c.z - h1.z; acc1 = fmaf(d, d, acc1);
        d = c.w - h1.w; acc1 = fmaf(d, d, acc1);
        d = c.x - h2.x; acc2 = fmaf(d, d, acc2);
        d = c.y - h2.y; acc2 = fmaf(d, d, acc2);
        d = c.z - h2.z; acc2 = fmaf(d, d, acc2);
        d = c.w - h2.w; acc2 = fmaf(d, d, acc2);
    }
    #pragma unroll
    for (int o = 16; o > 0; o >>= 1) {
        acc0 += __shfl_xor_sync(0xffffffffu, acc0, o);
        acc1 += __shfl_xor_sync(0xffffffffu, acc1, o);
        acc2 += __shfl_xor_sync(0xffffffffu, acc2, o);
    }
    if (lane == 0) {
        s_cd[warp     ] = sqrtf(acc0);
        s_cd[warp +  8] = sqrtf(acc1);
        s_cd[warp + 16] = sqrtf(acc2);
    }

    // ---- consume the TMA row (row 24+warp) from SMEM ----
    mbar_wait(mb, 0);
    {
        const float4* row = reinterpret_cast<const float4*>(s_tma + warp * HD);
        float acc = 0.f;
        #pragma unroll
        for (int i = 0; i < 8; i++) {
            const float4 h = row[lane + 32 * i];
            const float4 c = cv[i];
            float d;
            d = c.x - h.x; acc = fmaf(d, d, acc);
            d = c.y - h.y; acc = fmaf(d, d, acc);
            d = c.z - h.z; acc = fmaf(d, d, acc);
            d = c.w - h.w; acc = fmaf(d, d, acc);
        }
        #pragma unroll
        for (int o = 16; o > 0; o >>= 1)
            acc += __shfl_xor_sync(0xffffffffu, acc, o);
        if (lane == 0) s_cd[warp + 24] = sqrtf(acc);
    }
    __syncthreads();

    // ---- label counts (warp 0) + assemble x ----
    if (warp == 0) {
        const int v = s_vals[lane];
        int flag = (v != 0) ? 1 : 0;
        for (int j = 0; j < lane; j++)
            if (s_vals[j] == v) flag = 0;
        int c = flag;
        #pragma unroll
        for (int o = 1; o < 32; o <<= 1) {
            int t = __shfl_up_sync(0xffffffffu, c, o);
            if (lane >= o) c += t;
        }
        s_x[64 + lane] = (float)c;
        s_x[lane]      = s_cd[lane];
    }
    __syncthreads();

    // ---- MLP 96 -> 64 -> 1 ----
    if (tid < 64) {
        const float* w = W1 + tid * 96;   // 24KB: L2-resident across all CTAs
        float a = b1[tid];
        #pragma unroll
        for (int i = 0; i < 96; i++)
            a = fmaf(s_x[i], __ldg(w + i), a);
        s_h2[tid] = tanhf(a) * __ldg(W2 + tid);
    }
    __syncthreads();
    if (warp == 0) {
        float v = s_h2[lane] + s_h2[lane + 32];
        #pragma unroll
        for (int o = 16; o > 0; o >>= 1)
            v += __shfl_xor_sync(0xffffffffu, v, o);
        if (lane == 0)
            s_scale = 5.0f / (1.0f + expf(-(v + b2[0])));
    }
    __syncthreads();

    // ---- write outputs (concat: context_dist | new_distances) ----
    if (tid < KN) {
        const float cd = s_cd[tid] * s_scale;
        out[(size_t)b * KN + tid]                   = cd;
        out[(size_t)NB * KN + (size_t)b * KN + tid] = s_x[32 + tid] + cd;
    }
}

extern "C" void kernel_launch(void* const* d_in, const int* in_sizes, int n_in,
                              void* d_out, int out_size) {
    const int*   vals         = (const int*)  d_in[0];
    const float* distances    = (const float*)d_in[1];
    const float* cache_hidden = (const float*)d_in[2];
    const float* hiddens      = (const float*)d_in[3];
    const float* W1           = (const float*)d_in[4];
    const float* b1           = (const float*)d_in[5];
    const float* W2           = (const float*)d_in[6];
    const float* b2           = (const float*)d_in[7];
    float* out = (float*)d_out;

    mu_calc_kernel<<<NB, 256>>>(vals, distances, cache_hidden, hiddens,
                                W1, b1, W2, b2, out);
}

// round 13
// speedup vs baseline: 1.0939x; 1.0939x over previous
#include <cuda_runtime.h>
#include <math.h>

#define NB 8192
#define KN 32
#define HD 1024

// Streaming load: cache-streaming + 256B L2 prefetch hint (sequential stream,
// every prefetched byte is consumed by neighboring warps of the same CTA).
__device__ __forceinline__ float4 ldg_stream(const float4* p) {
    float4 v;
    asm volatile("ld.global.cs.L2::256B.v4.f32 {%0,%1,%2,%3}, [%4];"
                 : "=f"(v.x), "=f"(v.y), "=f"(v.z), "=f"(v.w)
                 : "l"(p));
    return v;
}

__global__ __launch_bounds__(256, 3)
void mu_calc_kernel(
    const int*   __restrict__ vals,
    const float* __restrict__ distances,
    const float* __restrict__ cache_hidden,
    const float* __restrict__ hiddens,
    const float* __restrict__ W1,
    const float* __restrict__ b1,
    const float* __restrict__ W2,
    const float* __restrict__ b2,
    float*       __restrict__ out)
{
    __shared__ float s_cache[HD];     // cache_hidden[b]
    __shared__ float s_cd[KN];        // unscaled context distances
    __shared__ float s_x[96];         // MLP input: [cd | dist | counts]
    __shared__ int   s_vals[KN];
    __shared__ float s_h2[64];        // hid[t]*W2[t]
    __shared__ float s_scale;

    const int b    = blockIdx.x;
    const int tid  = threadIdx.x;
    const int warp = tid >> 5;
    const int lane = tid & 31;

    // ---- stage per-batch data ----
    const float4* ch4 = reinterpret_cast<const float4*>(cache_hidden + (size_t)b * HD);
    reinterpret_cast<float4*>(s_cache)[tid] = ch4[tid];       // 256 * 16B = 4KB
    if (tid < KN) {
        s_vals[tid]   = vals[b * KN + tid];
        s_x[32 + tid] = distances[b * KN + tid];
    }
    __syncthreads();

    // ---- phase 1: L2 distances; each warp owns 4 consecutive k-rows,
    //      processed INTERLEAVED so all LDG.128 are independent.        ----
    const float4* sc4 = reinterpret_cast<const float4*>(s_cache);

    // cache row -> registers once; reused for all 4 rows (no LDS in hot loop)
    float4 cv[8];
    #pragma unroll
    for (int i = 0; i < 8; i++) cv[i] = sc4[lane + 32 * i];

    const int k0 = warp * 4;
    const float4* h4 = reinterpret_cast<const float4*>(
        hiddens + ((size_t)b * KN + k0) * HD);   // rows k0..k0+3 contiguous
    const int RS = HD / 4;                        // 256 float4 per row

    float acc0 = 0.f, acc1 = 0.f, acc2 = 0.f, acc3 = 0.f;
    #pragma unroll
    for (int i = 0; i < 8; i++) {
        const int off = lane + 32 * i;
        float4 h0 = ldg_stream(&h4[off]);
        float4 h1 = ldg_stream(&h4[RS     + off]);
        float4 h2 = ldg_stream(&h4[2 * RS + off]);
        float4 h3 = ldg_stream(&h4[3 * RS + off]);
        const float4 c = cv[i];
        float d;
        d = c.x - h0.x; acc0 = fmaf(d, d, acc0);
        d = c.y - h0.y; acc0 = fmaf(d, d, acc0);
        d = c.z - h0.z; acc0 = fmaf(d, d, acc0);
        d = c.w - h0.w; acc0 = fmaf(d, d, acc0);
        d = c.x - h1.x; acc1 = fmaf(d, d, acc1);
        d = c.y - h1.y; acc1 = fmaf(d, d, acc1);
        d = c.z - h1.z; acc1 = fmaf(d, d, acc1);
        d = c.w - h1.w; acc1 = fmaf(d, d, acc1);
        d = c.x - h2.x; acc2 = fmaf(d, d, acc2);
        d = c.y - h2.y; acc2 = fmaf(d, d, acc2);
        d = c.z - h2.z; acc2 = fmaf(d, d, acc2);
        d = c.w - h2.w; acc2 = fmaf(d, d, acc2);
        d = c.x - h3.x; acc3 = fmaf(d, d, acc3);
        d = c.y - h3.y; acc3 = fmaf(d, d, acc3);
        d = c.z - h3.z; acc3 = fmaf(d, d, acc3);
        d = c.w - h3.w; acc3 = fmaf(d, d, acc3);
    }
    #pragma unroll
    for (int o = 16; o > 0; o >>= 1) {
        acc0 += __shfl_xor_sync(0xffffffffu, acc0, o);
        acc1 += __shfl_xor_sync(0xffffffffu, acc1, o);
        acc2 += __shfl_xor_sync(0xffffffffu, acc2, o);
        acc3 += __shfl_xor_sync(0xffffffffu, acc3, o);
    }
    if (lane == 0) {
        s_cd[k0    ] = sqrtf(acc0);
        s_cd[k0 + 1] = sqrtf(acc1);
        s_cd[k0 + 2] = sqrtf(acc2);
        s_cd[k0 + 3] = sqrtf(acc3);
    }
    __syncthreads();

    // ---- phase 2: label counts (warp 0) + assemble x ----
    if (warp == 0) {
        const int v = s_vals[lane];
        int flag = (v != 0) ? 1 : 0;
        for (int j = 0; j < lane; j++)
            if (s_vals[j] == v) flag = 0;
        int c = flag;
        #pragma unroll
        for (int o = 1; o < 32; o <<= 1) {
            int t = __shfl_up_sync(0xffffffffu, c, o);
            if (lane >= o) c += t;
        }
        s_x[64 + lane] = (float)c;
        s_x[lane]      = s_cd[lane];
    }
    __syncthreads();

    // ---- phase 3: MLP 96 -> 64 -> 1 ----
    if (tid < 64) {
        const float* w = W1 + tid * 96;   // 24KB: L2-resident across all CTAs
        float a = b1[tid];
        #pragma unroll
        for (int i = 0; i < 96; i++)
            a = fmaf(s_x[i], __ldg(w + i), a);
        s_h2[tid] = tanhf(a) * __ldg(W2 + tid);
    }
    __syncthreads();
    if (warp == 0) {
        float v = s_h2[lane] + s_h2[lane + 32];
        #pragma unroll
        for (int o = 16; o > 0; o >>= 1)
            v += __shfl_xor_sync(0xffffffffu, v, o);
        if (lane == 0)
            s_scale = 5.0f / (1.0f + expf(-(v + b2[0])));
    }
    __syncthreads();

    // ---- phase 4: write outputs (concat: context_dist | new_distances) ----
    if (tid < KN) {
        const float cd = s_cd[tid] * s_scale;
        out[(size_t)b * KN + tid]                   = cd;
        out[(size_t)NB * KN + (size_t)b * KN + tid] = s_x[32 + tid] + cd;
    }
}

extern "C" void kernel_launch(void* const* d_in, const int* in_sizes, int n_in,
                              void* d_out, int out_size) {
    const int*   vals         = (const int*)  d_in[0];
    const float* distances    = (const float*)d_in[1];
    const float* cache_hidden = (const float*)d_in[2];
    const float* hiddens      = (const float*)d_in[3];
    const float* W1           = (const float*)d_in[4];
    const float* b1           = (const float*)d_in[5];
    const float* W2           = (const float*)d_in[6];
    const float* b2           = (const float*)d_in[7];
    float* out = (float*)d_out;

    mu_calc_kernel<<<NB, 256>>>(vals, distances, cache_hidden, hiddens,
                                W1, b1, W2, b2, out);
}